// round 1
// baseline (speedup 1.0000x reference)
#include <cuda_runtime.h>
#include <cuda_bf16.h>

#define N_NODES 50000
#define N_EDGES 800000
#define D 64

// Scratch (device globals — no allocation allowed)
__device__ float g_agg[(size_t)N_NODES * D];
__device__ float g_outdeg[N_NODES];
__device__ float g_indeg[N_NODES];
__device__ int   g_idx64;   // 1 if indices are int64, 0 if int32

// ---------------------------------------------------------------------------
// Index dtype detection: interpret first 64 entries as int64; if any falls
// outside [0, N_NODES) the buffer must be int32 (two packed int32s per int64
// read give values >= 2^32 with overwhelming probability).
__global__ void detect_kernel(const void* __restrict__ src) {
    __shared__ int bad;
    if (threadIdx.x == 0) bad = 0;
    __syncthreads();
    long long v = ((const long long*)src)[threadIdx.x];
    if (v < 0 || v >= (long long)N_NODES) atomicOr(&bad, 1);
    __syncthreads();
    if (threadIdx.x == 0) g_idx64 = bad ? 0 : 1;
}

__device__ __forceinline__ int load_idx(const void* __restrict__ p, int i, int is64) {
    if (is64) return (int)(((const long long*)p)[i]);
    return ((const int*)p)[i];
}

// ---------------------------------------------------------------------------
// Zero agg + degree arrays (out buffer is poisoned; agg must start at 0 each call)
__global__ void zero_kernel() {
    int i = blockIdx.x * blockDim.x + threadIdx.x;
    int stride = gridDim.x * blockDim.x;
    const int total4 = (N_NODES * D) / 4;
    float4 z = make_float4(0.f, 0.f, 0.f, 0.f);
    for (int k = i; k < total4; k += stride) ((float4*)g_agg)[k] = z;
    for (int k = i; k < N_NODES; k += stride) { g_outdeg[k] = 0.f; g_indeg[k] = 0.f; }
}

// ---------------------------------------------------------------------------
// Degrees: out-degree over src, in-degree over dst
__global__ void degree_kernel(const void* __restrict__ src, const void* __restrict__ dst) {
    int i = blockIdx.x * blockDim.x + threadIdx.x;
    int is64 = g_idx64;
    if (i < N_EDGES) {
        atomicAdd(&g_outdeg[load_idx(src, i, is64)], 1.0f);
        atomicAdd(&g_indeg[load_idx(dst, i, is64)], 1.0f);
    }
}

// ---------------------------------------------------------------------------
// Edge scatter: agg[dst] += x[src] * rsqrt(max(outdeg[src],1))
// 16 threads per edge, one float4 (16B) per thread, v4 global reduction.
__global__ void scatter_kernel(const float* __restrict__ x,
                               const void* __restrict__ src,
                               const void* __restrict__ dst) {
    int tid  = blockIdx.x * blockDim.x + threadIdx.x;
    int e    = tid >> 4;
    int lane = tid & 15;
    if (e >= N_EDGES) return;
    int is64 = g_idx64;
    int s = load_idx(src, e, is64);
    int d = load_idx(dst, e, is64);
    float scale = rsqrtf(fmaxf(g_outdeg[s], 1.0f));
    float4 v = ((const float4*)(x + (size_t)s * D))[lane];
    v.x *= scale; v.y *= scale; v.z *= scale; v.w *= scale;
    float* p = g_agg + (size_t)d * D + lane * 4;
    asm volatile("red.global.add.v4.f32 [%0], {%1,%2,%3,%4};"
                 :: "l"(p), "f"(v.x), "f"(v.y), "f"(v.z), "f"(v.w)
                 : "memory");
}

// ---------------------------------------------------------------------------
// Output: out[n] = (agg[n] * rsqrt(max(indeg[n],1))) @ W + b
// 4 nodes per 256-thread block. W transposed in padded shared (conflict-free).
__global__ void out_kernel(const float* __restrict__ W,
                           const float* __restrict__ b,
                           float* __restrict__ out) {
    __shared__ float sW[D][D + 1];   // sW[j][k] = W[k][j]
    __shared__ float sb[D];
    __shared__ float sA[4][D];

    int tid = threadIdx.x;            // 256 threads
    for (int idx = tid; idx < D * D; idx += 256) {
        int k = idx >> 6, j = idx & 63;
        sW[j][k] = W[k * D + j];
    }
    if (tid < D) sb[tid] = b[tid];

    int node0 = blockIdx.x * 4;
    {
        int n = node0 + (tid >> 6);
        sA[tid >> 6][tid & 63] = g_agg[(size_t)n * D + (tid & 63)];
    }
    __syncthreads();

    int ln = tid >> 6;       // local node 0..3
    int j  = tid & 63;       // output column
    int node = node0 + ln;
    float scale = rsqrtf(fmaxf(g_indeg[node], 1.0f));

    float acc = 0.f;
#pragma unroll
    for (int k = 0; k < D; k++) acc += sA[ln][k] * sW[j][k];
    out[(size_t)node * D + j] = acc * scale + sb[j];
}

// ---------------------------------------------------------------------------
extern "C" void kernel_launch(void* const* d_in, const int* in_sizes, int n_in,
                              void* d_out, int out_size) {
    const float* x   = (const float*)d_in[0];
    const void*  src = d_in[1];
    const void*  dst = d_in[2];
    const float* W   = (const float*)d_in[3];
    const float* b   = (const float*)d_in[4];
    float* out = (float*)d_out;

    detect_kernel<<<1, 64>>>(src);
    zero_kernel<<<2048, 256>>>();
    degree_kernel<<<(N_EDGES + 255) / 256, 256>>>(src, dst);
    scatter_kernel<<<(N_EDGES * 16) / 256, 256>>>(x, src, dst);
    out_kernel<<<N_NODES / 4, 256>>>(W, b, out);
}

// round 2
// speedup vs baseline: 1.2433x; 1.2433x over previous
#include <cuda_runtime.h>
#include <cuda_bf16.h>

#define N_NODES 50000
#define N_EDGES 800000
#define D 64

// Scratch (device globals — no allocation allowed)
__device__ float g_agg[(size_t)N_NODES * D];
__device__ float g_outdeg[N_NODES];
__device__ float g_indeg[N_NODES];
__device__ int   g_idx64;   // 1 if indices are int64, 0 if int32

__device__ __forceinline__ int load_idx(const void* __restrict__ p, int i, int is64) {
    if (is64) return (int)(((const long long*)p)[i]);
    return ((const int*)p)[i];
}

// ---------------------------------------------------------------------------
// Fused: zero agg + degree arrays, and (block 0) index-dtype detection.
__global__ void init_kernel(const void* __restrict__ src) {
    if (blockIdx.x == 0 && threadIdx.x == 0) {
        // Interpret first 64 entries as int64; any out-of-range => int32.
        const long long* q = (const long long*)src;
        bool bad = false;
#pragma unroll
        for (int i = 0; i < 64; i++) {
            long long v = q[i];
            bad |= (v < 0 || v >= (long long)N_NODES);
        }
        g_idx64 = bad ? 0 : 1;
    }
    int i = blockIdx.x * blockDim.x + threadIdx.x;
    int stride = gridDim.x * blockDim.x;
    const int total4 = (N_NODES * D) / 4;
    float4 z = make_float4(0.f, 0.f, 0.f, 0.f);
    for (int k = i; k < total4; k += stride) ((float4*)g_agg)[k] = z;
    for (int k = i; k < N_NODES; k += stride) { g_outdeg[k] = 0.f; g_indeg[k] = 0.f; }
}

// ---------------------------------------------------------------------------
// Degrees: out-degree over src, in-degree over dst (RED, no return).
__global__ void degree_kernel(const void* __restrict__ src, const void* __restrict__ dst) {
    int i = blockIdx.x * blockDim.x + threadIdx.x;
    int is64 = g_idx64;
    if (i < N_EDGES) {
        atomicAdd(&g_outdeg[load_idx(src, i, is64)], 1.0f);
        atomicAdd(&g_indeg[load_idx(dst, i, is64)], 1.0f);
    }
}

// ---------------------------------------------------------------------------
// Edge scatter: agg[dst] += x[src] * rsqrt(max(outdeg[src],1))
// 16 threads per edge; indices/scale loaded by group leader, shfl-broadcast.
__global__ void scatter_kernel(const float* __restrict__ x,
                               const void* __restrict__ src,
                               const void* __restrict__ dst) {
    int tid  = blockIdx.x * blockDim.x + threadIdx.x;
    int e    = tid >> 4;                  // grid sized exactly: e < N_EDGES always
    int lane = threadIdx.x & 31;
    int sub  = lane & 15;
    int leader = lane & 16;               // 0 or 16 within the warp
    int is64 = g_idx64;

    int s = 0, d = 0;
    float scale = 0.f;
    if (sub == 0) {
        s = load_idx(src, e, is64);
        d = load_idx(dst, e, is64);
        scale = rsqrtf(fmaxf(g_outdeg[s], 1.0f));
    }
    s     = __shfl_sync(0xffffffffu, s, leader);
    d     = __shfl_sync(0xffffffffu, d, leader);
    scale = __shfl_sync(0xffffffffu, scale, leader);

    float4 v = ((const float4*)(x + (size_t)s * D))[sub];
    v.x *= scale; v.y *= scale; v.z *= scale; v.w *= scale;
    float* p = g_agg + (size_t)d * D + sub * 4;
    asm volatile("red.global.add.v4.f32 [%0], {%1,%2,%3,%4};"
                 :: "l"(p), "f"(v.x), "f"(v.y), "f"(v.z), "f"(v.w)
                 : "memory");
}

// ---------------------------------------------------------------------------
// Persistent output GEMM: out[n] = (agg[n] * rsqrt(max(indeg[n],1))) @ W + b
// 592 blocks load W once into shared, then loop over 16-node tiles.
#define OUT_BLOCKS 592
#define TILE_NODES 16
#define N_TILES (N_NODES / TILE_NODES)   // 3125, exact

__global__ void out_kernel(const float* __restrict__ W,
                           const float* __restrict__ b,
                           float* __restrict__ out) {
    __shared__ float4 sW[D][D / 4];      // sW[k][j4] = W[k][4j4..4j4+3]
    __shared__ float  sb[D];
    __shared__ float  sA[TILE_NODES][D];

    int tid = threadIdx.x;               // 256 threads
    for (int idx = tid; idx < D * (D / 4); idx += 256) {
        int k = idx >> 4, j4 = idx & 15;
        sW[k][j4] = ((const float4*)(W + k * D))[j4];
    }
    if (tid < D) sb[tid] = b[tid];

    int ln = tid >> 4;                   // local node 0..15
    int j4 = tid & 15;                   // float4 column 0..15
    float4 bias = make_float4(sb[0], 0, 0, 0); // placeholder; real bias read after sync

    for (int tile = blockIdx.x; tile < N_TILES; tile += gridDim.x) {
        int node = tile * TILE_NODES + ln;
        float sc = rsqrtf(fmaxf(g_indeg[node], 1.0f));
        float4 a4 = ((const float4*)(g_agg + (size_t)node * D))[j4];
        a4.x *= sc; a4.y *= sc; a4.z *= sc; a4.w *= sc;
        __syncthreads();                 // prior tile reads done (also covers sW/sb init)
        ((float4*)sA[ln])[j4] = a4;
        __syncthreads();

        float4 acc = make_float4(0.f, 0.f, 0.f, 0.f);
#pragma unroll
        for (int k = 0; k < D; k++) {
            float a = sA[ln][k];
            float4 w = sW[k][j4];
            acc.x += a * w.x; acc.y += a * w.y;
            acc.z += a * w.z; acc.w += a * w.w;
        }
        bias = ((const float4*)sb)[j4];
        acc.x += bias.x; acc.y += bias.y; acc.z += bias.z; acc.w += bias.w;
        ((float4*)(out + (size_t)node * D))[j4] = acc;
    }
}

// ---------------------------------------------------------------------------
extern "C" void kernel_launch(void* const* d_in, const int* in_sizes, int n_in,
                              void* d_out, int out_size) {
    const float* x   = (const float*)d_in[0];
    const void*  src = d_in[1];
    const void*  dst = d_in[2];
    const float* W   = (const float*)d_in[3];
    const float* b   = (const float*)d_in[4];
    float* out = (float*)d_out;

    init_kernel<<<2048, 256>>>(src);
    degree_kernel<<<(N_EDGES + 255) / 256, 256>>>(src, dst);
    scatter_kernel<<<(N_EDGES * 16) / 256, 256>>>(x, src, dst);
    out_kernel<<<OUT_BLOCKS, 256>>>(W, b, out);
}

// round 3
// speedup vs baseline: 1.4739x; 1.1855x over previous
#include <cuda_runtime.h>
#include <cuda_bf16.h>

#define N_NODES 50000
#define N_EDGES 800000
#define D 64

// Scratch (device globals — no allocation allowed)
__device__ float g_agg[(size_t)N_NODES * D];
__device__ float g_outdeg[N_NODES];
__device__ float g_indeg[N_NODES];
__device__ int   g_idx64;   // 1 if indices are int64, 0 if int32

__device__ __forceinline__ int load_idx(const void* __restrict__ p, int i, int is64) {
    if (is64) return (int)(((const long long*)p)[i]);
    return ((const int*)p)[i];
}

// ---------------------------------------------------------------------------
// Fused: zero agg + degree arrays, and (block 0) index-dtype detection.
__global__ void init_kernel(const void* __restrict__ src) {
    if (blockIdx.x == 0 && threadIdx.x == 0) {
        const long long* q = (const long long*)src;
        bool bad = false;
#pragma unroll
        for (int i = 0; i < 64; i++) {
            long long v = q[i];
            bad |= (v < 0 || v >= (long long)N_NODES);
        }
        g_idx64 = bad ? 0 : 1;
    }
    int i = blockIdx.x * blockDim.x + threadIdx.x;
    int stride = gridDim.x * blockDim.x;
    const int total4 = (N_NODES * D) / 4;
    float4 z = make_float4(0.f, 0.f, 0.f, 0.f);
    for (int k = i; k < total4; k += stride) ((float4*)g_agg)[k] = z;
    for (int k = i; k < N_NODES; k += stride) { g_outdeg[k] = 0.f; g_indeg[k] = 0.f; }
}

// ---------------------------------------------------------------------------
// Degrees: out-degree over src, in-degree over dst (RED, no return).
__global__ void degree_kernel(const void* __restrict__ src, const void* __restrict__ dst) {
    int i = blockIdx.x * blockDim.x + threadIdx.x;
    int is64 = g_idx64;
    if (i < N_EDGES) {
        atomicAdd(&g_outdeg[load_idx(src, i, is64)], 1.0f);
        atomicAdd(&g_indeg[load_idx(dst, i, is64)], 1.0f);
    }
}

// ---------------------------------------------------------------------------
// Edge scatter: agg[dst] += x[src] * rsqrt(max(outdeg[src],1))
// 16 threads per edge; indices/scale loaded by group leader, shfl-broadcast.
__global__ void scatter_kernel(const float* __restrict__ x,
                               const void* __restrict__ src,
                               const void* __restrict__ dst) {
    int tid  = blockIdx.x * blockDim.x + threadIdx.x;
    int e    = tid >> 4;                  // grid sized exactly: e < N_EDGES always
    int lane = threadIdx.x & 31;
    int sub  = lane & 15;
    int leader = lane & 16;               // 0 or 16 within the warp
    int is64 = g_idx64;

    int s = 0, d = 0;
    float scale = 0.f;
    if (sub == 0) {
        s = load_idx(src, e, is64);
        d = load_idx(dst, e, is64);
        scale = rsqrtf(fmaxf(g_outdeg[s], 1.0f));
    }
    s     = __shfl_sync(0xffffffffu, s, leader);
    d     = __shfl_sync(0xffffffffu, d, leader);
    scale = __shfl_sync(0xffffffffu, scale, leader);

    float4 v = ((const float4*)(x + (size_t)s * D))[sub];
    v.x *= scale; v.y *= scale; v.z *= scale; v.w *= scale;
    float* p = g_agg + (size_t)d * D + sub * 4;
    asm volatile("red.global.add.v4.f32 [%0], {%1,%2,%3,%4};"
                 :: "l"(p), "f"(v.x), "f"(v.y), "f"(v.z), "f"(v.w)
                 : "memory");
}

// ---------------------------------------------------------------------------
// Output GEMM, register-tiled: out[n] = (agg[n]*rsqrt(max(indeg[n],1))) @ W + b
// 64 nodes per 256-thread block; each thread computes a 4-node x 4-col tile.
#define TILE_NODES 64
#define N_TILES ((N_NODES + TILE_NODES - 1) / TILE_NODES)   // 782 (last tile partial)

__global__ void __launch_bounds__(256) out_kernel(const float* __restrict__ W,
                                                  const float* __restrict__ b,
                                                  float* __restrict__ out) {
    __shared__ float4 sW[D][D / 4];          // sW[k][j4] = W[k][4j4..]
    __shared__ float4 sA[TILE_NODES][D / 4]; // sA[row][k4]
    __shared__ float  sb[D];

    int tid = threadIdx.x;
    int base = blockIdx.x * TILE_NODES;

    // Load W (1024 float4s) and bias
#pragma unroll
    for (int i = 0; i < 4; i++) {
        int idx = tid + i * 256;
        int k = idx >> 4, j4 = idx & 15;
        sW[k][j4] = ((const float4*)(W + k * D))[j4];
    }
    if (tid < D) sb[tid] = b[tid];

    // Load A tile (1024 float4s), zero-pad out-of-range rows
    float4 z = make_float4(0.f, 0.f, 0.f, 0.f);
#pragma unroll
    for (int i = 0; i < 4; i++) {
        int idx = tid + i * 256;
        int row = idx >> 4, k4 = idx & 15;
        int node = base + row;
        sA[row][k4] = (node < N_NODES) ? ((const float4*)(g_agg + (size_t)node * D))[k4] : z;
    }
    __syncthreads();

    int j4 = tid & 15;        // output float4 column
    int ng = tid >> 4;        // node group 0..15 -> rows ng*4 .. ng*4+3

    float4 acc0 = z, acc1 = z, acc2 = z, acc3 = z;

#pragma unroll
    for (int k4 = 0; k4 < 16; k4++) {
        float4 a0 = sA[ng * 4 + 0][k4];
        float4 a1 = sA[ng * 4 + 1][k4];
        float4 a2 = sA[ng * 4 + 2][k4];
        float4 a3 = sA[ng * 4 + 3][k4];
#pragma unroll
        for (int kk = 0; kk < 4; kk++) {
            float4 w = sW[k4 * 4 + kk][j4];
            float e0 = (&a0.x)[kk], e1 = (&a1.x)[kk], e2 = (&a2.x)[kk], e3 = (&a3.x)[kk];
            acc0.x += e0 * w.x; acc0.y += e0 * w.y; acc0.z += e0 * w.z; acc0.w += e0 * w.w;
            acc1.x += e1 * w.x; acc1.y += e1 * w.y; acc1.z += e1 * w.z; acc1.w += e1 * w.w;
            acc2.x += e2 * w.x; acc2.y += e2 * w.y; acc2.z += e2 * w.z; acc2.w += e2 * w.w;
            acc3.x += e3 * w.x; acc3.y += e3 * w.y; acc3.z += e3 * w.z; acc3.w += e3 * w.w;
        }
    }

    float4 bias = ((const float4*)sb)[j4];
    float4 accs[4] = {acc0, acc1, acc2, acc3};
#pragma unroll
    for (int nn = 0; nn < 4; nn++) {
        int node = base + ng * 4 + nn;
        if (node < N_NODES) {
            float sc = rsqrtf(fmaxf(g_indeg[node], 1.0f));
            float4 r;
            r.x = accs[nn].x * sc + bias.x;
            r.y = accs[nn].y * sc + bias.y;
            r.z = accs[nn].z * sc + bias.z;
            r.w = accs[nn].w * sc + bias.w;
            ((float4*)(out + (size_t)node * D))[j4] = r;
        }
    }
}

// ---------------------------------------------------------------------------
extern "C" void kernel_launch(void* const* d_in, const int* in_sizes, int n_in,
                              void* d_out, int out_size) {
    const float* x   = (const float*)d_in[0];
    const void*  src = d_in[1];
    const void*  dst = d_in[2];
    const float* W   = (const float*)d_in[3];
    const float* b   = (const float*)d_in[4];
    float* out = (float*)d_out;

    init_kernel<<<2048, 256>>>(src);
    degree_kernel<<<(N_EDGES + 255) / 256, 256>>>(src, dst);
    scatter_kernel<<<(N_EDGES * 16) / 256, 256>>>(x, src, dst);
    out_kernel<<<N_TILES, 256>>>(W, b, out);
}